// round 4
// baseline (speedup 1.0000x reference)
#include <cuda_runtime.h>

// ---------------------------------------------------------------------------
// GCN 4-layer forward on GB300 (sm_103a).
// R3: fused agg+GEMM kernels, colpair f32x2 GEMM (no packing movs),
// duplicated-x smem operands, pipelined gemm2 staging, fused readout.
// ---------------------------------------------------------------------------

#define MAX_N 100000
#define MAX_E 800000
#define MAX_G 500

__device__ float g_norm_out[MAX_N];
__device__ float g_norm_in[MAX_N];
__device__ int   g_deg_out[MAX_N];
__device__ int   g_deg_in[MAX_N];
__device__ int   g_row_ptr[MAX_N + 1];
__device__ int   g_cursor[MAX_N];
__device__ int   g_csr_src[MAX_E];
__device__ float g_h0[MAX_N * 128];
__device__ float g_h1[MAX_N * 64];
__device__ float g_gsum[MAX_G * 4];
__device__ int   g_gcnt[MAX_G];
__device__ int   g_bsum[128];
__device__ int   g_boff[128];

typedef unsigned long long ull;

__device__ __forceinline__ ull pk(float lo, float hi) {
    ull r; asm("mov.b64 %0, {%1,%2};" : "=l"(r) : "f"(lo), "f"(hi)); return r;
}
__device__ __forceinline__ void fma2(ull& d, ull a, ull b) {
    asm("fma.rn.f32x2 %0, %1, %2, %0;" : "+l"(d) : "l"(a), "l"(b));
}
__device__ __forceinline__ float2 upk(ull v) {
    float2 f; asm("mov.b64 {%0,%1}, %2;" : "=f"(f.x), "=f"(f.y) : "l"(v)); return f;
}

// ---------------------------------------------------------------------------
// Preprocessing
// ---------------------------------------------------------------------------
__global__ void zero_kernel(int n, int g) {
    int i = blockIdx.x * blockDim.x + threadIdx.x;
    if (i < n) { g_deg_out[i] = 0; g_deg_in[i] = 0; }
    if (i < g * 4) g_gsum[i] = 0.0f;
    if (i < g) g_gcnt[i] = 0;
}

__global__ void degree_kernel(const int* __restrict__ src,
                              const int* __restrict__ dst, int e) {
    int i = blockIdx.x * blockDim.x + threadIdx.x;
    if (i < e) {
        atomicAdd(&g_deg_out[src[i]], 1);
        atomicAdd(&g_deg_in[dst[i]], 1);
    }
}

// pass1 + norm computation fused
__global__ void scan_pass1(int n) {
    __shared__ int sw[8];
    int b = blockIdx.x, t = threadIdx.x;
    int i0 = b * 1024 + t * 4;
    int s = 0;
    #pragma unroll
    for (int j = 0; j < 4; j++) {
        int i = i0 + j;
        if (i < n) {
            int di = g_deg_in[i];
            s += di;
            g_norm_in[i]  = rsqrtf(fmaxf((float)di, 1.0f));
            g_norm_out[i] = rsqrtf(fmaxf((float)g_deg_out[i], 1.0f));
        }
    }
    #pragma unroll
    for (int o = 16; o; o >>= 1) s += __shfl_down_sync(0xffffffffu, s, o);
    if ((t & 31) == 0) sw[t >> 5] = s;
    __syncthreads();
    if (t < 8) {
        s = sw[t];
        #pragma unroll
        for (int o = 4; o; o >>= 1) s += __shfl_down_sync(0xffu, s, o);
        if (t == 0) g_bsum[b] = s;
    }
}

__global__ void scan_pass2(int nb, int n) {
    __shared__ int sw[4];
    int t = threadIdx.x, lane = t & 31, w = t >> 5;
    int v = (t < nb) ? g_bsum[t] : 0;
    int s = v;
    #pragma unroll
    for (int o = 1; o < 32; o <<= 1) {
        int x = __shfl_up_sync(0xffffffffu, s, o);
        if (lane >= o) s += x;
    }
    if (lane == 31) sw[w] = s;
    __syncthreads();
    int pre = 0;
    for (int j = 0; j < w; j++) pre += sw[j];
    int incl = s + pre;
    if (t < nb) g_boff[t] = incl - v;
    if (t == nb - 1) g_row_ptr[n] = incl;
}

__global__ void scan_pass3(int n) {
    __shared__ int swarp[8];
    int b = blockIdx.x, t = threadIdx.x, lane = t & 31, w = t >> 5;
    int i0 = b * 1024 + t * 4;
    int4 v = make_int4(0, 0, 0, 0);
    if (i0 + 3 < n) v = *(const int4*)&g_deg_in[i0];
    else {
        if (i0     < n) v.x = g_deg_in[i0];
        if (i0 + 1 < n) v.y = g_deg_in[i0 + 1];
        if (i0 + 2 < n) v.z = g_deg_in[i0 + 2];
        if (i0 + 3 < n) v.w = g_deg_in[i0 + 3];
    }
    int ts = v.x + v.y + v.z + v.w;
    int s = ts;
    #pragma unroll
    for (int o = 1; o < 32; o <<= 1) {
        int x = __shfl_up_sync(0xffffffffu, s, o);
        if (lane >= o) s += x;
    }
    if (lane == 31) swarp[w] = s;
    __syncthreads();
    if (w == 0 && lane < 8) {
        int ws = swarp[lane];
        #pragma unroll
        for (int o = 1; o < 8; o <<= 1) {
            int x = __shfl_up_sync(0xffu, ws, o);
            if (lane >= o) ws += x;
        }
        swarp[lane] = ws;
    }
    __syncthreads();
    int pre = (w > 0) ? swarp[w - 1] : 0;
    int e0 = g_boff[b] + pre + s - ts;
    int e1 = e0 + v.x, e2 = e1 + v.y, e3 = e2 + v.z;
    if (i0     < n) { g_row_ptr[i0]     = e0; g_cursor[i0]     = e0; }
    if (i0 + 1 < n) { g_row_ptr[i0 + 1] = e1; g_cursor[i0 + 1] = e1; }
    if (i0 + 2 < n) { g_row_ptr[i0 + 2] = e2; g_cursor[i0 + 2] = e2; }
    if (i0 + 3 < n) { g_row_ptr[i0 + 3] = e3; g_cursor[i0 + 3] = e3; }
}

__global__ void csr_fill_kernel(const int* __restrict__ src,
                                const int* __restrict__ dst, int e) {
    int i = blockIdx.x * blockDim.x + threadIdx.x;
    if (i < e) {
        int p = atomicAdd(&g_cursor[dst[i]], 1);
        g_csr_src[p] = src[i];
    }
}

// ---------------------------------------------------------------------------
// F1: gather(x * norm_out) -> *norm_in -> [64x64]@W1[64x128] + b1, relu -> h0
// Phase A writes the aggregated tile into smem as duplicated (v,v) f32x2.
// Phase B: colpair f32x2 GEMM, W pairs read directly from row-major smem.
// ---------------------------------------------------------------------------
__global__ void __launch_bounds__(256, 2)
fused_agg_gemm1(const float* __restrict__ x,
                const float* __restrict__ W1, const float* __restrict__ b1,
                float* __restrict__ out, int n) {
    extern __shared__ char smx[];
    float* sW = (float*)smx;                       // 64*128 f = 32KB
    ull*   sX = (ull*)(smx + 64 * 128 * 4);        // 64*64 ull = 32KB
    const int tid = threadIdx.x;
    for (int p = tid; p < 64 * 128 / 4; p += 256)
        ((float4*)sW)[p] = ((const float4*)W1)[p];
    int w = tid >> 5, l = tid & 31;
    int cg = tid & 15, rg = tid >> 4;
    int c0 = cg * 8;
    float4 bva = *(const float4*)&b1[c0];
    float4 bvb = *(const float4*)&b1[c0 + 4];

    int ntiles = (n + 63) / 64;
    for (int t = blockIdx.x; t < ntiles; t += gridDim.x) {
        int row0 = t * 64;
        __syncthreads();
        // ---- Phase A: 8 warps x 8 nodes, lane l holds dims l and l+32 ----
        #pragma unroll 1
        for (int i = 0; i < 8; i++) {
            int local = w * 8 + i;
            int node = row0 + local;
            float va = 0.f, vb = 0.f;
            if (node < n) {
                int beg = g_row_ptr[node], end = g_row_ptr[node + 1];
                float a0 = 0, a1 = 0, a2 = 0, a3 = 0;
                float c0_ = 0, c1 = 0, c2 = 0, c3 = 0;
                int e = beg;
                for (; e + 3 < end; e += 4) {
                    int s0 = g_csr_src[e],     s1 = g_csr_src[e + 1];
                    int s2 = g_csr_src[e + 2], s3 = g_csr_src[e + 3];
                    float n0 = g_norm_out[s0], n1 = g_norm_out[s1];
                    float n2 = g_norm_out[s2], n3 = g_norm_out[s3];
                    a0 = fmaf(x[s0 * 64 + l], n0, a0);  c0_ = fmaf(x[s0 * 64 + 32 + l], n0, c0_);
                    a1 = fmaf(x[s1 * 64 + l], n1, a1);  c1  = fmaf(x[s1 * 64 + 32 + l], n1, c1);
                    a2 = fmaf(x[s2 * 64 + l], n2, a2);  c2  = fmaf(x[s2 * 64 + 32 + l], n2, c2);
                    a3 = fmaf(x[s3 * 64 + l], n3, a3);  c3  = fmaf(x[s3 * 64 + 32 + l], n3, c3);
                }
                for (; e < end; e++) {
                    int s0 = g_csr_src[e]; float n0 = g_norm_out[s0];
                    a0 = fmaf(x[s0 * 64 + l], n0, a0);
                    c0_ = fmaf(x[s0 * 64 + 32 + l], n0, c0_);
                }
                float ni = g_norm_in[node];
                va = ((a0 + a1) + (a2 + a3)) * ni;
                vb = ((c0_ + c1) + (c2 + c3)) * ni;
            }
            sX[local * 64 + l]      = pk(va, va);
            sX[local * 64 + 32 + l] = pk(vb, vb);
        }
        __syncthreads();
        // ---- Phase B ----
        ull acc[4][4];
        #pragma unroll
        for (int r = 0; r < 4; r++)
            #pragma unroll
            for (int c = 0; c < 4; c++) acc[r][c] = 0ULL;
        #pragma unroll 4
        for (int k4 = 0; k4 < 16; k4++) {
            ull xr[4][4];
            #pragma unroll
            for (int r = 0; r < 4; r++) {
                const ull* xp = &sX[(rg * 4 + r) * 64 + k4 * 4];
                ulonglong2 xa = *(const ulonglong2*)xp;
                ulonglong2 xb = *(const ulonglong2*)(xp + 2);
                xr[r][0] = xa.x; xr[r][1] = xa.y; xr[r][2] = xb.x; xr[r][3] = xb.y;
            }
            #pragma unroll
            for (int kk = 0; kk < 4; kk++) {
                int k = k4 * 4 + kk;
                ulonglong2 w0 = *(const ulonglong2*)&sW[k * 128 + c0];
                ulonglong2 w1 = *(const ulonglong2*)&sW[k * 128 + c0 + 4];
                #pragma unroll
                for (int r = 0; r < 4; r++) {
                    fma2(acc[r][0], xr[r][kk], w0.x);
                    fma2(acc[r][1], xr[r][kk], w0.y);
                    fma2(acc[r][2], xr[r][kk], w1.x);
                    fma2(acc[r][3], xr[r][kk], w1.y);
                }
            }
        }
        #pragma unroll
        for (int r = 0; r < 4; r++) {
            int row = row0 + rg * 4 + r;
            if (row < n) {
                float2 f0 = upk(acc[r][0]), f1 = upk(acc[r][1]);
                float2 f2 = upk(acc[r][2]), f3 = upk(acc[r][3]);
                float4 va = make_float4(f0.x + bva.x, f0.y + bva.y, f1.x + bva.z, f1.y + bva.w);
                float4 vb = make_float4(f2.x + bvb.x, f2.y + bvb.y, f3.x + bvb.z, f3.y + bvb.w);
                va.x = fmaxf(va.x, 0.f); va.y = fmaxf(va.y, 0.f);
                va.z = fmaxf(va.z, 0.f); va.w = fmaxf(va.w, 0.f);
                vb.x = fmaxf(vb.x, 0.f); vb.y = fmaxf(vb.y, 0.f);
                vb.z = fmaxf(vb.z, 0.f); vb.w = fmaxf(vb.w, 0.f);
                *(float4*)&out[(size_t)row * 128 + c0]     = va;
                *(float4*)&out[(size_t)row * 128 + c0 + 4] = vb;
            }
        }
    }
}

// ---------------------------------------------------------------------------
// gemm2: h1 = (h0[N,128] @ W2[128,64]) * norm_out.  Pipelined gmem staging.
// ---------------------------------------------------------------------------
__global__ void __launch_bounds__(256, 1)
gemm2_kernel(const float* __restrict__ in, const float* __restrict__ W2,
             float* __restrict__ out, int n) {
    extern __shared__ char smx[];
    float* sW = (float*)smx;                       // 128*64 f = 32KB
    ull*   sX = (ull*)(smx + 128 * 64 * 4);        // 64*128 ull = 64KB
    const int tid = threadIdx.x;
    for (int p = tid; p < 128 * 64 / 4; p += 256)
        ((float4*)sW)[p] = ((const float4*)W2)[p];
    int cg = tid & 7, rg = tid >> 3;               // rg 0..31, rows rg*2, rg*2+1
    int c0 = cg * 8;

    int ntiles = (n + 63) / 64;
    float4 pf[8];
    int t = blockIdx.x;
    if (t < ntiles) {
        #pragma unroll
        for (int j = 0; j < 8; j++) {
            int idx = tid + j * 256;               // 2048 float4 per tile
            int row = t * 64 + (idx >> 5);
            pf[j] = (row < n) ? ((const float4*)in)[(size_t)row * 32 + (idx & 31)]
                              : make_float4(0.f, 0.f, 0.f, 0.f);
        }
    }
    for (; t < ntiles; t += gridDim.x) {
        int row0 = t * 64;
        __syncthreads();
        #pragma unroll
        for (int j = 0; j < 8; j++) {
            int idx = tid + j * 256;
            int r = idx >> 5, q = idx & 31;
            ull* d = &sX[r * 128 + q * 4];
            d[0] = pk(pf[j].x, pf[j].x); d[1] = pk(pf[j].y, pf[j].y);
            d[2] = pk(pf[j].z, pf[j].z); d[3] = pk(pf[j].w, pf[j].w);
        }
        __syncthreads();
        int tn = t + gridDim.x;
        if (tn < ntiles) {
            #pragma unroll
            for (int j = 0; j < 8; j++) {
                int idx = tid + j * 256;
                int row = tn * 64 + (idx >> 5);
                pf[j] = (row < n) ? ((const float4*)in)[(size_t)row * 32 + (idx & 31)]
                                  : make_float4(0.f, 0.f, 0.f, 0.f);
            }
        }
        ull acc[2][4];
        #pragma unroll
        for (int r = 0; r < 2; r++)
            #pragma unroll
            for (int c = 0; c < 4; c++) acc[r][c] = 0ULL;
        #pragma unroll 4
        for (int k4 = 0; k4 < 32; k4++) {
            ull xr[2][4];
            #pragma unroll
            for (int r = 0; r < 2; r++) {
                const ull* xp = &sX[(rg * 2 + r) * 128 + k4 * 4];
                ulonglong2 xa = *(const ulonglong2*)xp;
                ulonglong2 xb = *(const ulonglong2*)(xp + 2);
                xr[r][0] = xa.x; xr[r][1] = xa.y; xr[r][2] = xb.x; xr[r][3] = xb.y;
            }
            #pragma unroll
            for (int kk = 0; kk < 4; kk++) {
                int k = k4 * 4 + kk;
                ulonglong2 w0 = *(const ulonglong2*)&sW[k * 64 + c0];
                ulonglong2 w1 = *(const ulonglong2*)&sW[k * 64 + c0 + 4];
                #pragma unroll
                for (int r = 0; r < 2; r++) {
                    fma2(acc[r][0], xr[r][kk], w0.x);
                    fma2(acc[r][1], xr[r][kk], w0.y);
                    fma2(acc[r][2], xr[r][kk], w1.x);
                    fma2(acc[r][3], xr[r][kk], w1.y);
                }
            }
        }
        #pragma unroll
        for (int r = 0; r < 2; r++) {
            int row = row0 + rg * 2 + r;
            if (row < n) {
                float rs = g_norm_out[row];
                float2 f0 = upk(acc[r][0]), f1 = upk(acc[r][1]);
                float2 f2 = upk(acc[r][2]), f3 = upk(acc[r][3]);
                float4 va = make_float4(f0.x * rs, f0.y * rs, f1.x * rs, f1.y * rs);
                float4 vb = make_float4(f2.x * rs, f2.y * rs, f3.x * rs, f3.y * rs);
                *(float4*)&out[(size_t)row * 64 + c0]     = va;
                *(float4*)&out[(size_t)row * 64 + c0 + 4] = vb;
            }
        }
    }
}

// ---------------------------------------------------------------------------
// F2: agg(h1,64) *norm_in +b2, relu -> @W3[64,32] -> *norm_out -> h0 (32-dim)
// ---------------------------------------------------------------------------
__global__ void __launch_bounds__(256, 2)
fused_agg_gemm3(const float* __restrict__ hin,
                const float* __restrict__ W3, const float* __restrict__ b2,
                float* __restrict__ out, int n) {
    extern __shared__ char smx[];
    float* sW = (float*)smx;                       // 64*32 f = 8KB
    ull*   sX = (ull*)(smx + 64 * 32 * 4);         // 64*64 ull = 32KB
    const int tid = threadIdx.x;
    for (int p = tid; p < 64 * 32 / 4; p += 256)
        ((float4*)sW)[p] = ((const float4*)W3)[p];
    int w = tid >> 5, l = tid & 31;
    float blo = b2[l], bhi = b2[l + 32];
    int cg = tid & 3, rg = tid >> 2;               // rg = row 0..63
    int c0 = cg * 8;

    int ntiles = (n + 63) / 64;
    for (int t = blockIdx.x; t < ntiles; t += gridDim.x) {
        int row0 = t * 64;
        __syncthreads();
        #pragma unroll 1
        for (int i = 0; i < 8; i++) {
            int local = w * 8 + i;
            int node = row0 + local;
            float va = 0.f, vb = 0.f;
            if (node < n) {
                int beg = g_row_ptr[node], end = g_row_ptr[node + 1];
                float a0 = 0, a1 = 0, a2 = 0, a3 = 0;
                float c0_ = 0, c1 = 0, c2 = 0, c3 = 0;
                int e = beg;
                for (; e + 3 < end; e += 4) {
                    int s0 = g_csr_src[e],     s1 = g_csr_src[e + 1];
                    int s2 = g_csr_src[e + 2], s3 = g_csr_src[e + 3];
                    a0 += hin[s0 * 64 + l];  c0_ += hin[s0 * 64 + 32 + l];
                    a1 += hin[s1 * 64 + l];  c1  += hin[s1 * 64 + 32 + l];
                    a2 += hin[s2 * 64 + l];  c2  += hin[s2 * 64 + 32 + l];
                    a3 += hin[s3 * 64 + l];  c3  += hin[s3 * 64 + 32 + l];
                }
                for (; e < end; e++) {
                    int s0 = g_csr_src[e];
                    a0 += hin[s0 * 64 + l]; c0_ += hin[s0 * 64 + 32 + l];
                }
                float ni = g_norm_in[node];
                va = fmaxf(fmaf(((a0 + a1) + (a2 + a3)), ni, blo), 0.f);
                vb = fmaxf(fmaf(((c0_ + c1) + (c2 + c3)), ni, bhi), 0.f);
            }
            sX[local * 64 + l]      = pk(va, va);
            sX[local * 64 + 32 + l] = pk(vb, vb);
        }
        __syncthreads();
        ull acc[4];
        acc[0] = acc[1] = acc[2] = acc[3] = 0ULL;
        #pragma unroll 4
        for (int k4 = 0; k4 < 16; k4++) {
            const ull* xp = &sX[rg * 64 + k4 * 4];
            ulonglong2 xa = *(const ulonglong2*)xp;
            ulonglong2 xb = *(const ulonglong2*)(xp + 2);
            ull xr[4] = {xa.x, xa.y, xb.x, xb.y};
            #pragma unroll
            for (int kk = 0; kk < 4; kk++) {
                int k = k4 * 4 + kk;
                ulonglong2 w0 = *(const ulonglong2*)&sW[k * 32 + c0];
                ulonglong2 w1 = *(const ulonglong2*)&sW[k * 32 + c0 + 4];
                fma2(acc[0], xr[kk], w0.x);
                fma2(acc[1], xr[kk], w0.y);
                fma2(acc[2], xr[kk], w1.x);
                fma2(acc[3], xr[kk], w1.y);
            }
        }
        int row = row0 + rg;
        if (row < n) {
            float rs = g_norm_out[row];
            float2 f0 = upk(acc[0]), f1 = upk(acc[1]);
            float2 f2 = upk(acc[2]), f3 = upk(acc[3]);
            float4 va = make_float4(f0.x * rs, f0.y * rs, f1.x * rs, f1.y * rs);
            float4 vb = make_float4(f2.x * rs, f2.y * rs, f3.x * rs, f3.y * rs);
            *(float4*)&out[(size_t)row * 32 + c0]     = va;
            *(float4*)&out[(size_t)row * 32 + c0 + 4] = vb;
        }
    }
}

// ---------------------------------------------------------------------------
// F3: agg(h0,32) *norm_in +b3, relu -> @W4[32,4] -> *norm_out -> h1 (4-dim)
// Phase A stores with XOR swizzle so Phase B (row per thread) is low-conflict.
// ---------------------------------------------------------------------------
__global__ void __launch_bounds__(256, 2)
fused_agg_gemm4(const float* __restrict__ hin,
                const float* __restrict__ W4, const float* __restrict__ b3,
                float* __restrict__ out, int n) {
    extern __shared__ char smx[];
    float* sXf = (float*)smx;                      // 256*32 f = 32KB
    float* sW4 = (float*)(smx + 256 * 32 * 4);     // 128 f
    const int tid = threadIdx.x;
    if (tid < 128) sW4[tid] = W4[tid];
    int w = tid >> 5, l = tid & 31;
    float bl = b3[l];

    int ntiles = (n + 255) / 256;
    for (int t = blockIdx.x; t < ntiles; t += gridDim.x) {
        int row0 = t * 256;
        __syncthreads();
        #pragma unroll 1
        for (int i = 0; i < 32; i++) {
            int local = w * 32 + i;
            int node = row0 + local;
            float va = 0.f;
            if (node < n) {
                int beg = g_row_ptr[node], end = g_row_ptr[node + 1];
                float a0 = 0, a1 = 0, a2 = 0, a3 = 0;
                int e = beg;
                for (; e + 3 < end; e += 4) {
                    a0 += hin[g_csr_src[e] * 32 + l];
                    a1 += hin[g_csr_src[e + 1] * 32 + l];
                    a2 += hin[g_csr_src[e + 2] * 32 + l];
                    a3 += hin[g_csr_src[e + 3] * 32 + l];
                }
                for (; e < end; e++) a0 += hin[g_csr_src[e] * 32 + l];
                va = fmaxf(fmaf(((a0 + a1) + (a2 + a3)), g_norm_in[node], bl), 0.f);
            }
            // swizzled store: k=l -> float4-group (l>>2) ^ (local&7), elem l&3
            sXf[local * 32 + (((l >> 2) ^ (local & 7)) << 2) + (l & 3)] = va;
        }
        __syncthreads();
        int row = row0 + tid;
        if (row < n) {
            float4 acc = make_float4(0.f, 0.f, 0.f, 0.f);
            #pragma unroll
            for (int k4 = 0; k4 < 8; k4++) {
                float4 xv = *(const float4*)&sXf[tid * 32 + ((k4 ^ (tid & 7)) << 2)];
                float4 w0 = *(const float4*)&sW4[(k4 * 4 + 0) * 4];
                float4 w1 = *(const float4*)&sW4[(k4 * 4 + 1) * 4];
                float4 w2 = *(const float4*)&sW4[(k4 * 4 + 2) * 4];
                float4 w3 = *(const float4*)&sW4[(k4 * 4 + 3) * 4];
                acc.x = fmaf(xv.x, w0.x, fmaf(xv.y, w1.x, fmaf(xv.z, w2.x, fmaf(xv.w, w3.x, acc.x))));
                acc.y = fmaf(xv.x, w0.y, fmaf(xv.y, w1.y, fmaf(xv.z, w2.y, fmaf(xv.w, w3.y, acc.y))));
                acc.z = fmaf(xv.x, w0.z, fmaf(xv.y, w1.z, fmaf(xv.z, w2.z, fmaf(xv.w, w3.z, acc.z))));
                acc.w = fmaf(xv.x, w0.w, fmaf(xv.y, w1.w, fmaf(xv.z, w2.w, fmaf(xv.w, w3.w, acc.w))));
            }
            float rs = g_norm_out[row];
            acc.x *= rs; acc.y *= rs; acc.z *= rs; acc.w *= rs;
            *(float4*)&out[(size_t)row * 4] = acc;
        }
    }
}

// ---------------------------------------------------------------------------
// F4: agg(h1,4) *norm_in + b4 -> per-graph atomic sum + count (sorted gids)
// ---------------------------------------------------------------------------
__global__ void agg4_readout(const float* __restrict__ hin,
                             const float* __restrict__ b4,
                             const int* __restrict__ gid, int n) {
    int warp = (blockIdx.x * blockDim.x + threadIdx.x) >> 5;
    int lane = threadIdx.x & 31;
    int node = warp * 8 + (lane >> 2);
    int l = lane & 3;
    float v = 0.f;
    int g = 0;
    bool valid = node < n;
    if (valid) {
        int beg = g_row_ptr[node], end = g_row_ptr[node + 1];
        float a0 = 0, a1 = 0, a2 = 0, a3 = 0;
        int e = beg;
        for (; e + 3 < end; e += 4) {
            a0 += hin[g_csr_src[e] * 4 + l];
            a1 += hin[g_csr_src[e + 1] * 4 + l];
            a2 += hin[g_csr_src[e + 2] * 4 + l];
            a3 += hin[g_csr_src[e + 3] * 4 + l];
        }
        for (; e < end; e++) a0 += hin[g_csr_src[e] * 4 + l];
        v = fmaf(((a0 + a1) + (a2 + a3)), g_norm_in[node], b4[l]);
        g = gid[node];
    }
    unsigned act = __ballot_sync(0xffffffffu, valid);
    if (act == 0xffffffffu) {
        int g0 = __shfl_sync(0xffffffffu, g, 0);
        if (__all_sync(0xffffffffu, g == g0)) {
            v += __shfl_xor_sync(0xffffffffu, v, 4);
            v += __shfl_xor_sync(0xffffffffu, v, 8);
            v += __shfl_xor_sync(0xffffffffu, v, 16);
            if (lane < 4) atomicAdd(&g_gsum[g0 * 4 + lane], v);
            if (lane == 0) atomicAdd(&g_gcnt[g0], 8);
            return;
        }
    }
    if (valid) {
        atomicAdd(&g_gsum[g * 4 + l], v);
        if (l == 0) atomicAdd(&g_gcnt[g], 1);
    }
}

__global__ void graph_mean_kernel(float* __restrict__ out, int g) {
    int i = blockIdx.x * blockDim.x + threadIdx.x;
    if (i < g * 4) {
        float c = fmaxf((float)g_gcnt[i >> 2], 1.0f);
        out[i] = g_gsum[i] / c;
    }
}

// ---------------------------------------------------------------------------
extern "C" void kernel_launch(void* const* d_in, const int* in_sizes, int n_in,
                              void* d_out, int out_size) {
    const float* x  = (const float*)d_in[0];
    const float* W1 = (const float*)d_in[1];
    const float* b1 = (const float*)d_in[2];
    const float* W2 = (const float*)d_in[3];
    const float* b2 = (const float*)d_in[4];
    const float* W3 = (const float*)d_in[5];
    const float* b3 = (const float*)d_in[6];
    const float* W4 = (const float*)d_in[7];
    const float* b4 = (const float*)d_in[8];
    const int* src = (const int*)d_in[9];
    const int* dst = (const int*)d_in[10];
    const int* gid = (const int*)d_in[11];
    float* out = (float*)d_out;

    int n = in_sizes[0] / 64;
    int e = in_sizes[9];
    int g = out_size / 4;

    float *h0, *h1;
    cudaGetSymbolAddress((void**)&h0, g_h0);
    cudaGetSymbolAddress((void**)&h1, g_h1);

    const int T = 256;
    auto blocks = [](int work, int t) { return (work + t - 1) / t; };

    const int SM_F1 = 64 * 128 * 4 + 64 * 64 * 8;   // 65536
    const int SM_G2 = 128 * 64 * 4 + 64 * 128 * 8;  // 98304
    const int SM_F2 = 64 * 32 * 4 + 64 * 64 * 8;    // 40960
    const int SM_F3 = 256 * 32 * 4 + 128 * 4;       // 33280
    cudaFuncSetAttribute((const void*)fused_agg_gemm1,
                         cudaFuncAttributeMaxDynamicSharedMemorySize, SM_F1);
    cudaFuncSetAttribute((const void*)gemm2_kernel,
                         cudaFuncAttributeMaxDynamicSharedMemorySize, SM_G2);
    cudaFuncSetAttribute((const void*)fused_agg_gemm3,
                         cudaFuncAttributeMaxDynamicSharedMemorySize, SM_F2);
    cudaFuncSetAttribute((const void*)fused_agg_gemm4,
                         cudaFuncAttributeMaxDynamicSharedMemorySize, SM_F3);

    int nb = (n + 1023) / 1024;
    zero_kernel<<<blocks(n, T), T>>>(n, g);
    degree_kernel<<<blocks(e, T), T>>>(src, dst, e);
    scan_pass1<<<nb, 256>>>(n);
    scan_pass2<<<1, 128>>>(nb, n);
    scan_pass3<<<nb, 256>>>(n);
    csr_fill_kernel<<<blocks(e, T), T>>>(src, dst, e);

    fused_agg_gemm1<<<296, 256, SM_F1>>>(x, W1, b1, h0, n);
    gemm2_kernel<<<148, 256, SM_G2>>>(h0, W2, h1, n);
    fused_agg_gemm3<<<296, 256, SM_F2>>>(h1, W3, b2, h0, n);
    fused_agg_gemm4<<<296, 256, SM_F3>>>(h0, W4, b3, h1, n);
    int warps4 = (n + 7) / 8;
    agg4_readout<<<blocks(warps4 * 32, T), T>>>(h1, b4, gid, n);
    graph_mean_kernel<<<blocks(g * 4, T), T>>>(out, g);
}

// round 5
// speedup vs baseline: 1.2608x; 1.2608x over previous
#include <cuda_runtime.h>

// ---------------------------------------------------------------------------
// GCN 4-layer forward on GB300 (sm_103a).
// R4: R2 structure (standalone high-occupancy agg + standalone GEMMs),
// colpair f32x2 GEMM (W row-major in smem, X duplicated at staging),
// norm_out folded into layer-1 gather, fused scan+norm, fused final readout.
// ---------------------------------------------------------------------------

#define MAX_N 100000
#define MAX_E 800000
#define MAX_G 500

__device__ float g_norm_out[MAX_N];
__device__ float g_norm_in[MAX_N];
__device__ int   g_deg_out[MAX_N];
__device__ int   g_deg_in[MAX_N];
__device__ int   g_row_ptr[MAX_N + 1];
__device__ int   g_cursor[MAX_N];
__device__ int   g_csr_src[MAX_E];
__device__ float g_h0[MAX_N * 128];
__device__ float g_h1[MAX_N * 64];
__device__ float g_gsum[MAX_G * 4];
__device__ int   g_gcnt[MAX_G];
__device__ int   g_bsum[128];
__device__ int   g_boff[128];

typedef unsigned long long ull;

__device__ __forceinline__ ull pk(float lo, float hi) {
    ull r; asm("mov.b64 %0, {%1,%2};" : "=l"(r) : "f"(lo), "f"(hi)); return r;
}
__device__ __forceinline__ void fma2(ull& d, ull a, ull b) {
    asm("fma.rn.f32x2 %0, %1, %2, %0;" : "+l"(d) : "l"(a), "l"(b));
}
__device__ __forceinline__ float2 upk(ull v) {
    float2 f; asm("mov.b64 {%0,%1}, %2;" : "=f"(f.x), "=f"(f.y) : "l"(v)); return f;
}

// ---------------------------------------------------------------------------
// Preprocessing
// ---------------------------------------------------------------------------
__global__ void zero_kernel(int n, int g) {
    int i = blockIdx.x * blockDim.x + threadIdx.x;
    if (i < n) { g_deg_out[i] = 0; g_deg_in[i] = 0; }
    if (i < g * 4) g_gsum[i] = 0.0f;
    if (i < g) g_gcnt[i] = 0;
}

__global__ void degree_kernel(const int* __restrict__ src,
                              const int* __restrict__ dst, int e) {
    int i = blockIdx.x * blockDim.x + threadIdx.x;
    if (i < e) {
        atomicAdd(&g_deg_out[src[i]], 1);
        atomicAdd(&g_deg_in[dst[i]], 1);
    }
}

// pass1 + norm computation fused
__global__ void scan_pass1(int n) {
    __shared__ int sw[8];
    int b = blockIdx.x, t = threadIdx.x;
    int i0 = b * 1024 + t * 4;
    int s = 0;
    #pragma unroll
    for (int j = 0; j < 4; j++) {
        int i = i0 + j;
        if (i < n) {
            int di = g_deg_in[i];
            s += di;
            g_norm_in[i]  = rsqrtf(fmaxf((float)di, 1.0f));
            g_norm_out[i] = rsqrtf(fmaxf((float)g_deg_out[i], 1.0f));
        }
    }
    #pragma unroll
    for (int o = 16; o; o >>= 1) s += __shfl_down_sync(0xffffffffu, s, o);
    if ((t & 31) == 0) sw[t >> 5] = s;
    __syncthreads();
    if (t < 8) {
        s = sw[t];
        #pragma unroll
        for (int o = 4; o; o >>= 1) s += __shfl_down_sync(0xffu, s, o);
        if (t == 0) g_bsum[b] = s;
    }
}

__global__ void scan_pass2(int nb, int n) {
    __shared__ int sw[4];
    int t = threadIdx.x, lane = t & 31, w = t >> 5;
    int v = (t < nb) ? g_bsum[t] : 0;
    int s = v;
    #pragma unroll
    for (int o = 1; o < 32; o <<= 1) {
        int x = __shfl_up_sync(0xffffffffu, s, o);
        if (lane >= o) s += x;
    }
    if (lane == 31) sw[w] = s;
    __syncthreads();
    int pre = 0;
    for (int j = 0; j < w; j++) pre += sw[j];
    int incl = s + pre;
    if (t < nb) g_boff[t] = incl - v;
    if (t == nb - 1) g_row_ptr[n] = incl;
}

__global__ void scan_pass3(int n) {
    __shared__ int swarp[8];
    int b = blockIdx.x, t = threadIdx.x, lane = t & 31, w = t >> 5;
    int i0 = b * 1024 + t * 4;
    int4 v = make_int4(0, 0, 0, 0);
    if (i0 + 3 < n) v = *(const int4*)&g_deg_in[i0];
    else {
        if (i0     < n) v.x = g_deg_in[i0];
        if (i0 + 1 < n) v.y = g_deg_in[i0 + 1];
        if (i0 + 2 < n) v.z = g_deg_in[i0 + 2];
        if (i0 + 3 < n) v.w = g_deg_in[i0 + 3];
    }
    int ts = v.x + v.y + v.z + v.w;
    int s = ts;
    #pragma unroll
    for (int o = 1; o < 32; o <<= 1) {
        int x = __shfl_up_sync(0xffffffffu, s, o);
        if (lane >= o) s += x;
    }
    if (lane == 31) swarp[w] = s;
    __syncthreads();
    if (w == 0 && lane < 8) {
        int ws = swarp[lane];
        #pragma unroll
        for (int o = 1; o < 8; o <<= 1) {
            int x = __shfl_up_sync(0xffu, ws, o);
            if (lane >= o) ws += x;
        }
        swarp[lane] = ws;
    }
    __syncthreads();
    int pre = (w > 0) ? swarp[w - 1] : 0;
    int e0 = g_boff[b] + pre + s - ts;
    int e1 = e0 + v.x, e2 = e1 + v.y, e3 = e2 + v.z;
    if (i0     < n) { g_row_ptr[i0]     = e0; g_cursor[i0]     = e0; }
    if (i0 + 1 < n) { g_row_ptr[i0 + 1] = e1; g_cursor[i0 + 1] = e1; }
    if (i0 + 2 < n) { g_row_ptr[i0 + 2] = e2; g_cursor[i0 + 2] = e2; }
    if (i0 + 3 < n) { g_row_ptr[i0 + 3] = e3; g_cursor[i0 + 3] = e3; }
}

__global__ void csr_fill_kernel(const int* __restrict__ src,
                                const int* __restrict__ dst, int e) {
    int i = blockIdx.x * blockDim.x + threadIdx.x;
    if (i < e) {
        int p = atomicAdd(&g_cursor[dst[i]], 1);
        g_csr_src[p] = src[i];
    }
}

// ---------------------------------------------------------------------------
// Gather-aggregate (standalone, warp-per-node, 4-way MLP unroll).
// SRCSCALE: multiply each gathered row by g_norm_out[src] (layer 1, hin = x).
// ---------------------------------------------------------------------------
template<int DIM, bool RELU, bool HASB, bool SRCSCALE>
__global__ void agg_kernel(const float* __restrict__ hin,
                           float* __restrict__ hout,
                           const float* __restrict__ bias, int n) {
    constexpr int LPN = (DIM >= 32) ? 32 : DIM;
    constexpr int NPW = 32 / LPN;
    int warp = (blockIdx.x * blockDim.x + threadIdx.x) >> 5;
    int lane = threadIdx.x & 31;
    int node = warp * NPW + (lane / LPN);
    int l = lane % LPN;
    if (node >= n) return;
    int beg = g_row_ptr[node];
    int end = g_row_ptr[node + 1];
    float ni = g_norm_in[node];
    if (DIM == 64) {
        const float* base = hin + l * 2;
        float2 a0 = {0, 0}, a1 = {0, 0}, a2 = {0, 0}, a3 = {0, 0};
        int e = beg;
        for (; e + 3 < end; e += 4) {
            int s0 = g_csr_src[e],     s1 = g_csr_src[e + 1];
            int s2 = g_csr_src[e + 2], s3 = g_csr_src[e + 3];
            float2 v0 = *(const float2*)(base + s0 * 64);
            float2 v1 = *(const float2*)(base + s1 * 64);
            float2 v2 = *(const float2*)(base + s2 * 64);
            float2 v3 = *(const float2*)(base + s3 * 64);
            if (SRCSCALE) {
                float n0 = g_norm_out[s0], n1 = g_norm_out[s1];
                float n2 = g_norm_out[s2], n3 = g_norm_out[s3];
                a0.x = fmaf(v0.x, n0, a0.x); a0.y = fmaf(v0.y, n0, a0.y);
                a1.x = fmaf(v1.x, n1, a1.x); a1.y = fmaf(v1.y, n1, a1.y);
                a2.x = fmaf(v2.x, n2, a2.x); a2.y = fmaf(v2.y, n2, a2.y);
                a3.x = fmaf(v3.x, n3, a3.x); a3.y = fmaf(v3.y, n3, a3.y);
            } else {
                a0.x += v0.x; a0.y += v0.y; a1.x += v1.x; a1.y += v1.y;
                a2.x += v2.x; a2.y += v2.y; a3.x += v3.x; a3.y += v3.y;
            }
        }
        for (; e < end; e++) {
            int s0 = g_csr_src[e];
            float2 v = *(const float2*)(base + s0 * 64);
            if (SRCSCALE) {
                float n0 = g_norm_out[s0];
                a0.x = fmaf(v.x, n0, a0.x); a0.y = fmaf(v.y, n0, a0.y);
            } else { a0.x += v.x; a0.y += v.y; }
        }
        float ax = (a0.x + a1.x) + (a2.x + a3.x);
        float ay = (a0.y + a1.y) + (a2.y + a3.y);
        ax *= ni; ay *= ni;
        if (HASB) { ax += bias[l * 2]; ay += bias[l * 2 + 1]; }
        if (RELU) { ax = fmaxf(ax, 0.0f); ay = fmaxf(ay, 0.0f); }
        float2 o; o.x = ax; o.y = ay;
        *(float2*)&hout[node * 64 + l * 2] = o;
    } else {
        const float* base = hin + l;
        float a0 = 0, a1 = 0, a2 = 0, a3 = 0;
        int e = beg;
        for (; e + 3 < end; e += 4) {
            int s0 = g_csr_src[e],     s1 = g_csr_src[e + 1];
            int s2 = g_csr_src[e + 2], s3 = g_csr_src[e + 3];
            a0 += base[s0 * DIM]; a1 += base[s1 * DIM];
            a2 += base[s2 * DIM]; a3 += base[s3 * DIM];
        }
        for (; e < end; e++) a0 += base[g_csr_src[e] * DIM];
        float a = (a0 + a1) + (a2 + a3);
        a *= ni;
        if (HASB) a += bias[l];
        if (RELU) a = fmaxf(a, 0.0f);
        hout[node * DIM + l] = a;
    }
}

// ---------------------------------------------------------------------------
// Colpair f32x2 GEMM: out[N,M] = op(in[N,K] @ W[K,M]).
// W row-major in smem (adjacent cols read as ull = f32x2 operand).
// X staged duplicated (v,v) per element. 8 cols x RPT rows per thread.
// Register prefetch of next tile overlaps gmem latency with compute.
// ---------------------------------------------------------------------------
template<int K, int M, int RPT, bool RELU, bool BIAS, bool RSCALE, int MAXB>
__global__ void __launch_bounds__(256, MAXB)
gemm_kernel(const float* __restrict__ in, const float* __restrict__ W,
            const float* __restrict__ bias, float* __restrict__ out, int n) {
    constexpr int THREADS = 256;
    constexpr int CG = M / 8;              // col-groups (8 cols per thread)
    constexpr int RG = THREADS / CG;
    constexpr int RTILE = RG * RPT;
    constexpr int KV = K / 4;              // float4 per row
    constexpr int LOADS = RTILE * KV / THREADS;

    extern __shared__ char smx[];
    float* sW = (float*)smx;               // K*M floats, row-major
    ull*   sX = (ull*)(smx + (size_t)K * M * 4);  // RTILE*K ull, duplicated

    const int tid = threadIdx.x;
    for (int p = tid; p < K * M / 4; p += THREADS)
        ((float4*)sW)[p] = ((const float4*)W)[p];

    int cg = tid % CG;
    int rg = tid / CG;
    int c0 = cg * 8;
    int rbase = rg * RPT;

    float4 bva = make_float4(0.f, 0.f, 0.f, 0.f);
    float4 bvb = make_float4(0.f, 0.f, 0.f, 0.f);
    if (BIAS) { bva = *(const float4*)&bias[c0]; bvb = *(const float4*)&bias[c0 + 4]; }

    int ntiles = (n + RTILE - 1) / RTILE;
    float4 pf[LOADS];
    int t = blockIdx.x;
    if (t < ntiles) {
        #pragma unroll
        for (int j = 0; j < LOADS; j++) {
            int idx = tid + j * THREADS;
            int row = t * RTILE + idx / KV;
            pf[j] = (row < n) ? ((const float4*)in)[(size_t)row * KV + idx % KV]
                              : make_float4(0.f, 0.f, 0.f, 0.f);
        }
    }
    for (; t < ntiles; t += gridDim.x) {
        int row0 = t * RTILE;
        __syncthreads();
        #pragma unroll
        for (int j = 0; j < LOADS; j++) {
            int idx = tid + j * THREADS;
            ull* d = &sX[(idx / KV) * K + (idx % KV) * 4];
            d[0] = pk(pf[j].x, pf[j].x); d[1] = pk(pf[j].y, pf[j].y);
            d[2] = pk(pf[j].z, pf[j].z); d[3] = pk(pf[j].w, pf[j].w);
        }
        __syncthreads();
        int tn = t + gridDim.x;
        if (tn < ntiles) {
            #pragma unroll
            for (int j = 0; j < LOADS; j++) {
                int idx = tid + j * THREADS;
                int row = tn * RTILE + idx / KV;
                pf[j] = (row < n) ? ((const float4*)in)[(size_t)row * KV + idx % KV]
                                  : make_float4(0.f, 0.f, 0.f, 0.f);
            }
        }
        ull acc[RPT][4];
        #pragma unroll
        for (int r = 0; r < RPT; r++)
            #pragma unroll
            for (int c = 0; c < 4; c++) acc[r][c] = 0ULL;

        #pragma unroll 4
        for (int k4 = 0; k4 < K / 4; k4++) {
            ull xr[RPT][4];
            #pragma unroll
            for (int r = 0; r < RPT; r++) {
                const ull* xp = &sX[(rbase + r) * K + k4 * 4];
                ulonglong2 xa = *(const ulonglong2*)xp;
                ulonglong2 xb = *(const ulonglong2*)(xp + 2);
                xr[r][0] = xa.x; xr[r][1] = xa.y; xr[r][2] = xb.x; xr[r][3] = xb.y;
            }
            #pragma unroll
            for (int kk = 0; kk < 4; kk++) {
                int k = k4 * 4 + kk;
                ulonglong2 w0 = *(const ulonglong2*)&sW[k * M + c0];
                ulonglong2 w1 = *(const ulonglong2*)&sW[k * M + c0 + 4];
                #pragma unroll
                for (int r = 0; r < RPT; r++) {
                    fma2(acc[r][0], xr[r][kk], w0.x);
                    fma2(acc[r][1], xr[r][kk], w0.y);
                    fma2(acc[r][2], xr[r][kk], w1.x);
                    fma2(acc[r][3], xr[r][kk], w1.y);
                }
            }
        }
        #pragma unroll
        for (int r = 0; r < RPT; r++) {
            int row = row0 + rbase + r;
            if (row < n) {
                float2 f0 = upk(acc[r][0]), f1 = upk(acc[r][1]);
                float2 f2 = upk(acc[r][2]), f3 = upk(acc[r][3]);
                float4 va = make_float4(f0.x, f0.y, f1.x, f1.y);
                float4 vb = make_float4(f2.x, f2.y, f3.x, f3.y);
                if (BIAS) {
                    va.x += bva.x; va.y += bva.y; va.z += bva.z; va.w += bva.w;
                    vb.x += bvb.x; vb.y += bvb.y; vb.z += bvb.z; vb.w += bvb.w;
                }
                if (RSCALE) {
                    float rs = g_norm_out[row];
                    va.x *= rs; va.y *= rs; va.z *= rs; va.w *= rs;
                    vb.x *= rs; vb.y *= rs; vb.z *= rs; vb.w *= rs;
                }
                if (RELU) {
                    va.x = fmaxf(va.x, 0.f); va.y = fmaxf(va.y, 0.f);
                    va.z = fmaxf(va.z, 0.f); va.w = fmaxf(va.w, 0.f);
                    vb.x = fmaxf(vb.x, 0.f); vb.y = fmaxf(vb.y, 0.f);
                    vb.z = fmaxf(vb.z, 0.f); vb.w = fmaxf(vb.w, 0.f);
                }
                *(float4*)&out[(size_t)row * M + c0]     = va;
                *(float4*)&out[(size_t)row * M + c0 + 4] = vb;
            }
        }
    }
}

// Final tiny GEMM: K=32, M=4, one row per thread, fused norm_out.
__global__ void gemm4_kernel(const float* __restrict__ in,
                             const float* __restrict__ W,
                             float* __restrict__ out, int n) {
    __shared__ float4 sw[32];
    if (threadIdx.x < 32) sw[threadIdx.x] = *(const float4*)&W[threadIdx.x * 4];
    __syncthreads();
    int r = blockIdx.x * blockDim.x + threadIdx.x;
    if (r >= n) return;
    const float* x = in + (size_t)r * 32;
    float4 acc = make_float4(0.f, 0.f, 0.f, 0.f);
    #pragma unroll
    for (int k4 = 0; k4 < 8; k4++) {
        float4 xv = *(const float4*)&x[k4 * 4];
        float4 w0 = sw[k4 * 4], w1 = sw[k4 * 4 + 1], w2 = sw[k4 * 4 + 2], w3 = sw[k4 * 4 + 3];
        acc.x = fmaf(xv.x, w0.x, fmaf(xv.y, w1.x, fmaf(xv.z, w2.x, fmaf(xv.w, w3.x, acc.x))));
        acc.y = fmaf(xv.x, w0.y, fmaf(xv.y, w1.y, fmaf(xv.z, w2.y, fmaf(xv.w, w3.y, acc.y))));
        acc.z = fmaf(xv.x, w0.z, fmaf(xv.y, w1.z, fmaf(xv.z, w2.z, fmaf(xv.w, w3.z, acc.z))));
        acc.w = fmaf(xv.x, w0.w, fmaf(xv.y, w1.w, fmaf(xv.z, w2.w, fmaf(xv.w, w3.w, acc.w))));
    }
    float s = g_norm_out[r];
    acc.x *= s; acc.y *= s; acc.z *= s; acc.w *= s;
    *(float4*)&out[(size_t)r * 4] = acc;
}

// ---------------------------------------------------------------------------
// Final: agg(h,4) * norm_in + b4 -> per-graph sum + count (gids sorted).
// ---------------------------------------------------------------------------
__global__ void agg4_readout(const float* __restrict__ hin,
                             const float* __restrict__ b4,
                             const int* __restrict__ gid, int n) {
    int warp = (blockIdx.x * blockDim.x + threadIdx.x) >> 5;
    int lane = threadIdx.x & 31;
    int node = warp * 8 + (lane >> 2);
    int l = lane & 3;
    float v = 0.f;
    int g = 0;
    bool valid = node < n;
    if (valid) {
        int beg = g_row_ptr[node], end = g_row_ptr[node + 1];
        float a0 = 0, a1 = 0, a2 = 0, a3 = 0;
        int e = beg;
        for (; e + 3 < end; e += 4) {
            a0 += hin[g_csr_src[e] * 4 + l];
            a1 += hin[g_csr_src[e + 1] * 4 + l];
            a2 += hin[g_csr_src[e + 2] * 4 + l];
            a3 += hin[g_csr_src[e + 3] * 4 + l];
        }
        for (; e < end; e++) a0 += hin[g_csr_src[e] * 4 + l];
        v = fmaf(((a0 + a1) + (a2 + a3)), g_norm_in[node], b4[l]);
        g = gid[node];
    }
    unsigned act = __ballot_sync(0xffffffffu, valid);
    if (act == 0xffffffffu) {
        int g0 = __shfl_sync(0xffffffffu, g, 0);
        if (__all_sync(0xffffffffu, g == g0)) {
            v += __shfl_xor_sync(0xffffffffu, v, 4);
            v += __shfl_xor_sync(0xffffffffu, v, 8);
            v += __shfl_xor_sync(0xffffffffu, v, 16);
            if (lane < 4) atomicAdd(&g_gsum[g0 * 4 + lane], v);
            if (lane == 0) atomicAdd(&g_gcnt[g0], 8);
            return;
        }
    }
    if (valid) {
        atomicAdd(&g_gsum[g * 4 + l], v);
        if (l == 0) atomicAdd(&g_gcnt[g], 1);
    }
}

__global__ void graph_mean_kernel(float* __restrict__ out, int g) {
    int i = blockIdx.x * blockDim.x + threadIdx.x;
    if (i < g * 4) {
        float c = fmaxf((float)g_gcnt[i >> 2], 1.0f);
        out[i] = g_gsum[i] / c;
    }
}

// ---------------------------------------------------------------------------
extern "C" void kernel_launch(void* const* d_in, const int* in_sizes, int n_in,
                              void* d_out, int out_size) {
    const float* x  = (const float*)d_in[0];
    const float* W1 = (const float*)d_in[1];
    const float* b1 = (const float*)d_in[2];
    const float* W2 = (const float*)d_in[3];
    const float* b2 = (const float*)d_in[4];
    const float* W3 = (const float*)d_in[5];
    const float* b3 = (const float*)d_in[6];
    const float* W4 = (const float*)d_in[7];
    const float* b4 = (const float*)d_in[8];
    const int* src = (const int*)d_in[9];
    const int* dst = (const int*)d_in[10];
    const int* gid = (const int*)d_in[11];
    float* out = (float*)d_out;

    int n = in_sizes[0] / 64;
    int e = in_sizes[9];
    int g = out_size / 4;

    float *h0, *h1;
    cudaGetSymbolAddress((void**)&h0, g_h0);
    cudaGetSymbolAddress((void**)&h1, g_h1);

    const int T = 256;
    auto blocks = [](int work, int t) { return (work + t - 1) / t; };
    auto agg_grid = [&](int npw) {
        int warps = (n + npw - 1) / npw;
        return (warps * 32 + T - 1) / T;
    };

    // GEMM instantiations: <K, M, RPT, RELU, BIAS, RSCALE, MAXB>
    // gemm1: 64 -> 128, +b1, relu.        RTILE=64.  smem 32K(W)+32K(X)=64K
    // gemm2: 128 -> 64, *norm_out.        RTILE=64.  smem 32K(W)+64K(X)=96K
    // gemm3: 64 -> 32,  *norm_out.        RTILE=64.  smem  8K(W)+32K(X)=40K
    const int SM1 = 64 * 128 * 4 + 64 * 64 * 8;
    const int SM2 = 128 * 64 * 4 + 64 * 128 * 8;
    const int SM3 = 64 * 32 * 4 + 64 * 64 * 8;
    cudaFuncSetAttribute((const void*)gemm_kernel<64, 128, 4, true, true, false, 2>,
                         cudaFuncAttributeMaxDynamicSharedMemorySize, SM1);
    cudaFuncSetAttribute((const void*)gemm_kernel<128, 64, 2, false, false, true, 1>,
                         cudaFuncAttributeMaxDynamicSharedMemorySize, SM2);
    cudaFuncSetAttribute((const void*)gemm_kernel<64, 32, 1, false, false, true, 4>,
                         cudaFuncAttributeMaxDynamicSharedMemorySize, SM3);

    int nb = (n + 1023) / 1024;
    zero_kernel<<<blocks(n, T), T>>>(n, g);
    degree_kernel<<<blocks(e, T), T>>>(src, dst, e);
    scan_pass1<<<nb, 256>>>(n);
    scan_pass2<<<1, 128>>>(nb, n);
    scan_pass3<<<nb, 256>>>(n);
    csr_fill_kernel<<<blocks(e, T), T>>>(src, dst, e);

    // Layer 1: agg(x * norm_out) -> *norm_in -> @W1 + b1, relu
    agg_kernel<64, false, false, true><<<agg_grid(1), T>>>(x, h1, nullptr, n);
    gemm_kernel<64, 128, 4, true, true, false, 2><<<296, 256, SM1>>>(h1, W1, b1, h0, n);

    // Layer 2: (h @ W2) * norm_out -> agg -> *norm_in + b2, relu
    gemm_kernel<128, 64, 2, false, false, true, 1><<<148, 256, SM2>>>(h0, W2, nullptr, h1, n);
    agg_kernel<64, true, true, false><<<agg_grid(1), T>>>(h1, h0, b2, n);

    // Layer 3
    gemm_kernel<64, 32, 1, false, false, true, 4><<<592, 256, SM3>>>(h0, W3, nullptr, h1, n);
    agg_kernel<32, true, true, false><<<agg_grid(1), T>>>(h1, h0, b3, n);

    // Layer 4 + readout
    gemm4_kernel<<<blocks(n, T), T>>>(h0, W4, h1, n);
    int warps4 = (n + 7) / 8;
    agg4_readout<<<blocks(warps4 * 32, T), T>>>(h1, b4, gid, n);
    graph_mean_kernel<<<blocks(g * 4, T), T>>>(out, g);
}